// round 1
// baseline (speedup 1.0000x reference)
#include <cuda_runtime.h>
#include <math.h>

#define LOG_SQRT_2PI 0.91893853320467274178f  // 0.5*log(2*pi)

__device__ float g_partials[64];
__device__ float g_prior;

// ---------------------------------------------------------------------------
// K1: per-sample prior terms -> per-block partial sums
// One thread per sample (B samples). Grid: ceil(B/256) blocks x 256.
// ---------------------------------------------------------------------------
__global__ void prior_partial_kernel(const float* __restrict__ predAbun,
                                     const float* __restrict__ sigmaPrior,
                                     int B)
{
    int s = blockIdx.x * blockDim.x + threadIdx.x;
    float acc = 0.0f;
    if (s < B) {
        float p[7], sg[7];
#pragma unroll
        for (int i = 0; i < 7; ++i) {
            p[i]  = predAbun[s * 7 + i];
            sg[i] = sigmaPrior[s * 7 + i];
        }
        // molecule order: O2, N2, H2, CO2, H2O, CH4, NH3
        float O2v = p[0], N2v = p[1], H2v = p[2], CO2v = p[3],
              H2Ov = p[4], CH4v = p[5], NH3v = p[6];
        float H = 2.0f * H2v + 2.0f * H2Ov + 3.0f * NH3v + 4.0f * CH4v;
        float C = CO2v + CH4v;
        float O = 2.0f * O2v + 2.0f * CO2v + H2Ov;
        float N = 2.0f * N2v + NH3v;

        float mu[7] = {0.f, 0.f, 0.f, 0.f, 0.f, 0.f, 0.f};

        bool condA = H > 2.0f * O + 4.0f * C;
        if (condA) {
            if (3.0f * N < H - 2.0f * O - 4.0f * C) {
                // A1: D = H - N - 2C
                float D = H - N - 2.0f * C;
                float inv = 1.0f / D;
                mu[2] = (H - 2.0f * O - 4.0f * C - 3.0f * N) * inv;
                mu[4] = 2.0f * O * inv;
                mu[5] = 2.0f * C * inv;
                mu[6] = 2.0f * N * inv;
            } else {
                // A2: D = H + 2C + 3N + 4O
                float D = H + 2.0f * C + 3.0f * N + 4.0f * O;
                float inv = 1.0f / D;
                mu[1] = (3.0f * N + 4.0f * C + 2.0f * O - H) * inv;
                mu[4] = 6.0f * O * inv;
                mu[5] = 6.0f * C * inv;
                mu[6] = (2.0f * H - 8.0f * C - 4.0f * O) * inv;
            }
        } else if (2.0f * O > H + 4.0f * C) {
            // B: D = H + 2O + 2N
            float D = H + 2.0f * O + 2.0f * N;
            float inv = 1.0f / D;
            mu[0] = (2.0f * O - H - 4.0f * C) * inv;
            mu[1] = 2.0f * N * inv;
            mu[3] = 4.0f * C * inv;
            mu[4] = 2.0f * H * inv;
        } else if (fabsf(H + C + O + N - 1.0f) < 1e-3f) {
            // C: D1 = H+2O+2N, D2 = 2H+4O+4N
            float D1 = H + 2.0f * O + 2.0f * N;
            float D2 = 2.0f * H + 4.0f * O + 4.0f * N;
            float i1 = 1.0f / D1, i2 = 1.0f / D2;
            mu[1] = 2.0f * N * i1;
            mu[3] = (2.0f * O + 4.0f * C - H) * i2;
            mu[4] = (H + 2.0f * O - 4.0f * C) * i1;
            mu[5] = (H - 2.0f * O + 4.0f * C) * i2;
        }
        // else: unclassified -> mu stays 0

#pragma unroll
        for (int i = 0; i < 7; ++i) {
            float d = p[i] - mu[i];
            acc += LOG_SQRT_2PI + logf(sg[i]) + d * d / (2.0f * sg[i] * sg[i]);
        }
    }

    // block reduce (256 threads = 8 warps)
    __shared__ float warp_sums[8];
    int lane = threadIdx.x & 31;
    int wid  = threadIdx.x >> 5;
#pragma unroll
    for (int off = 16; off > 0; off >>= 1)
        acc += __shfl_down_sync(0xFFFFFFFFu, acc, off);
    if (lane == 0) warp_sums[wid] = acc;
    __syncthreads();
    if (wid == 0) {
        float v = (lane < 8) ? warp_sums[lane] : 0.0f;
#pragma unroll
        for (int off = 4; off > 0; off >>= 1)
            v += __shfl_down_sync(0xFFFFFFFFu, v, off);
        if (lane == 0) g_partials[blockIdx.x] = v;
    }
}

// ---------------------------------------------------------------------------
// K2: reduce partials -> g_prior (= sum / B)
// ---------------------------------------------------------------------------
__global__ void prior_finalize_kernel(int nPartials, float invB)
{
    int lane = threadIdx.x;  // 32 threads
    float v = 0.0f;
    for (int i = lane; i < nPartials; i += 32) v += g_partials[i];
#pragma unroll
    for (int off = 16; off > 0; off >>= 1)
        v += __shfl_down_sync(0xFFFFFFFFu, v, off);
    if (lane == 0) g_prior = v * invB;
}

// ---------------------------------------------------------------------------
// K3: per-row MSE + prior. One block per row, float4 streaming.
// S must be divisible by 4 (S = 4096 here).
// ---------------------------------------------------------------------------
__global__ void posterior_kernel(const float4* __restrict__ yReal4,
                                 const float4* __restrict__ ySim4,
                                 float* __restrict__ out,
                                 int S4 /* = S/4 */, float scale /* = 1/(2*sigma^2*S) */)
{
    int row = blockIdx.x;
    const float4* r = yReal4 + (long long)row * S4;
    const float4* s = ySim4  + (long long)row * S4;

    float acc = 0.0f;
    for (int j = threadIdx.x; j < S4; j += blockDim.x) {
        float4 a = __ldg(r + j);
        float4 b = __ldg(s + j);
        float d0 = a.x - b.x, d1 = a.y - b.y, d2 = a.z - b.z, d3 = a.w - b.w;
        acc = fmaf(d0, d0, acc);
        acc = fmaf(d1, d1, acc);
        acc = fmaf(d2, d2, acc);
        acc = fmaf(d3, d3, acc);
    }

    __shared__ float warp_sums[8];
    int lane = threadIdx.x & 31;
    int wid  = threadIdx.x >> 5;
#pragma unroll
    for (int off = 16; off > 0; off >>= 1)
        acc += __shfl_down_sync(0xFFFFFFFFu, acc, off);
    if (lane == 0) warp_sums[wid] = acc;
    __syncthreads();
    if (wid == 0) {
        float v = (lane < 8) ? warp_sums[lane] : 0.0f;
#pragma unroll
        for (int off = 4; off > 0; off >>= 1)
            v += __shfl_down_sync(0xFFFFFFFFu, v, off);
        if (lane == 0) out[row] = v * scale + g_prior;
    }
}

// ---------------------------------------------------------------------------
// launch
// inputs (metadata order): predAbun [B,7] f32, sigmaPrior [B,7] f32,
//                          yReal [B,S] f32, ySim [B,S] f32
// output: posterior [B] f32
// ---------------------------------------------------------------------------
extern "C" void kernel_launch(void* const* d_in, const int* in_sizes, int n_in,
                              void* d_out, int out_size)
{
    const float* predAbun   = (const float*)d_in[0];
    const float* sigmaPrior = (const float*)d_in[1];
    const float* yReal      = (const float*)d_in[2];
    const float* ySim       = (const float*)d_in[3];
    float* out = (float*)d_out;

    int B = in_sizes[0] / 7;           // 8192
    int S = in_sizes[2] / B;           // 4096
    int S4 = S / 4;

    const float SIGMA_L = 0.1f;
    float scale = 1.0f / (2.0f * SIGMA_L * SIGMA_L * (float)S);  // mse/(2σ²) with sum->mean folded

    int nBlocks1 = (B + 255) / 256;    // 32 for B=8192 (g_partials sized 64)
    prior_partial_kernel<<<nBlocks1, 256>>>(predAbun, sigmaPrior, B);
    prior_finalize_kernel<<<1, 32>>>(nBlocks1, 1.0f / (float)B);
    posterior_kernel<<<B, 256>>>((const float4*)yReal, (const float4*)ySim,
                                 out, S4, scale);
}

// round 2
// speedup vs baseline: 1.1016x; 1.1016x over previous
#include <cuda_runtime.h>
#include <math.h>

#define LOG_SQRT_2PI 0.91893853320467274178f  // 0.5*log(2*pi)

// sync/scratch globals — zero-initialized at module load; the kernel's last
// block resets them to zero so every graph replay starts clean.
__device__ float          g_partials[256];
__device__ int            g_counter;        // # prior blocks that published a partial
__device__ volatile int   g_flag;           // prior ready
__device__ volatile float g_prior;
__device__ int            g_done;           // # blocks fully finished

// ---------------------------------------------------------------------------
// Fused kernel: grid = B blocks x 256 threads.
//   Phase 1 (blocks 0..nPriorBlocks-1): per-sample prior NLL -> partials; the
//     last prior block to arrive reduces partials -> g_prior, sets g_flag.
//   Phase 2 (all blocks): row MSE via float4 streaming; writer thread waits on
//     g_flag (already set by then), writes out[row] = mse*scale + prior.
//   Epilogue: last block to finish resets the sync globals for the next replay.
// ---------------------------------------------------------------------------
__global__ void fused_posterior_kernel(const float*  __restrict__ predAbun,
                                       const float*  __restrict__ sigmaPrior,
                                       const float4* __restrict__ yReal4,
                                       const float4* __restrict__ ySim4,
                                       float* __restrict__ out,
                                       int B, int S4, float scale, float invB,
                                       int nPriorBlocks)
{
    const int row  = blockIdx.x;
    const int tid  = threadIdx.x;
    const int lane = tid & 31;
    const int wid  = tid >> 5;

    __shared__ float warp_sums[8];

    // ---------------- Phase 1: prior (first nPriorBlocks blocks only) -------
    if (row < nPriorBlocks) {
        int s = row * 256 + tid;
        float acc = 0.0f;
        if (s < B) {
            float p[7], sg[7];
#pragma unroll
            for (int i = 0; i < 7; ++i) {
                p[i]  = predAbun[s * 7 + i];
                sg[i] = sigmaPrior[s * 7 + i];
            }
            // molecule order: O2, N2, H2, CO2, H2O, CH4, NH3
            float H = 2.0f * p[2] + 2.0f * p[4] + 3.0f * p[6] + 4.0f * p[5];
            float C = p[3] + p[5];
            float O = 2.0f * p[0] + 2.0f * p[3] + p[4];
            float N = 2.0f * p[1] + p[6];

            float mu[7] = {0.f, 0.f, 0.f, 0.f, 0.f, 0.f, 0.f};

            bool condA = H > 2.0f * O + 4.0f * C;
            if (condA) {
                if (3.0f * N < H - 2.0f * O - 4.0f * C) {
                    float D = H - N - 2.0f * C;
                    float inv = __fdividef(1.0f, D);
                    mu[2] = (H - 2.0f * O - 4.0f * C - 3.0f * N) * inv;
                    mu[4] = 2.0f * O * inv;
                    mu[5] = 2.0f * C * inv;
                    mu[6] = 2.0f * N * inv;
                } else {
                    float D = H + 2.0f * C + 3.0f * N + 4.0f * O;
                    float inv = __fdividef(1.0f, D);
                    mu[1] = (3.0f * N + 4.0f * C + 2.0f * O - H) * inv;
                    mu[4] = 6.0f * O * inv;
                    mu[5] = 6.0f * C * inv;
                    mu[6] = (2.0f * H - 8.0f * C - 4.0f * O) * inv;
                }
            } else if (2.0f * O > H + 4.0f * C) {
                float D = H + 2.0f * O + 2.0f * N;
                float inv = __fdividef(1.0f, D);
                mu[0] = (2.0f * O - H - 4.0f * C) * inv;
                mu[1] = 2.0f * N * inv;
                mu[3] = 4.0f * C * inv;
                mu[4] = 2.0f * H * inv;
            } else if (fabsf(H + C + O + N - 1.0f) < 1e-3f) {
                float D1 = H + 2.0f * O + 2.0f * N;
                float D2 = 2.0f * H + 4.0f * O + 4.0f * N;
                float i1 = __fdividef(1.0f, D1);
                float i2 = __fdividef(1.0f, D2);
                mu[1] = 2.0f * N * i1;
                mu[3] = (2.0f * O + 4.0f * C - H) * i2;
                mu[4] = (H + 2.0f * O - 4.0f * C) * i1;
                mu[5] = (H - 2.0f * O + 4.0f * C) * i2;
            }
            // else unclassified -> mu stays 0

            // sum of logs == log of product (sigmas in [0.1, 0.6], no under/overflow)
            float prod = sg[0] * sg[1] * sg[2] * sg[3] * sg[4] * sg[5] * sg[6];
            acc = 7.0f * LOG_SQRT_2PI + __logf(prod);
#pragma unroll
            for (int i = 0; i < 7; ++i) {
                float d = p[i] - mu[i];
                acc += __fdividef(0.5f * d * d, sg[i] * sg[i]);
            }
        }

        // block reduce (8 warps)
#pragma unroll
        for (int off = 16; off > 0; off >>= 1)
            acc += __shfl_down_sync(0xFFFFFFFFu, acc, off);
        if (lane == 0) warp_sums[wid] = acc;
        __syncthreads();
        if (tid == 0) {
            float v = 0.0f;
#pragma unroll
            for (int w = 0; w < 8; ++w) v += warp_sums[w];
            g_partials[row] = v;
            __threadfence();
            int c = atomicAdd(&g_counter, 1);
            if (c == nPriorBlocks - 1) {
                // last prior block publishes the scalar prior (fixed-order sum
                // by a single thread -> deterministic)
                float t = 0.0f;
                for (int i = 0; i < nPriorBlocks; ++i) t += g_partials[i];
                g_prior = t * invB;
                __threadfence();
                g_flag = 1;
            }
        }
        __syncthreads();  // shared memory reused below
    }

    // ---------------- Phase 2: row MSE (all blocks) -------------------------
    const float4* r = yReal4 + (long long)row * S4;
    const float4* s = ySim4  + (long long)row * S4;

    float acc = 0.0f;
    for (int j = tid; j < S4; j += 256) {
        float4 a = __ldg(r + j);
        float4 b = __ldg(s + j);
        float d0 = a.x - b.x, d1 = a.y - b.y, d2 = a.z - b.z, d3 = a.w - b.w;
        acc = fmaf(d0, d0, acc);
        acc = fmaf(d1, d1, acc);
        acc = fmaf(d2, d2, acc);
        acc = fmaf(d3, d3, acc);
    }

#pragma unroll
    for (int off = 16; off > 0; off >>= 1)
        acc += __shfl_down_sync(0xFFFFFFFFu, acc, off);
    if (lane == 0) warp_sums[wid] = acc;
    __syncthreads();

    if (tid == 0) {
        float v = 0.0f;
#pragma unroll
        for (int w = 0; w < 8; ++w) v += warp_sums[w];
        // wait for prior (set long before any block finishes 32KB of loads)
        while (g_flag == 0) { }
        float pr = g_prior;
        out[row] = v * scale + pr;

        // epilogue: last block to finish resets sync globals for next replay
        int d = atomicAdd(&g_done, 1);
        if (d == gridDim.x - 1) {
            g_counter = 0;
            g_flag    = 0;
            g_done    = 0;
        }
    }
}

// ---------------------------------------------------------------------------
// launch
// inputs (metadata order): predAbun [B,7] f32, sigmaPrior [B,7] f32,
//                          yReal [B,S] f32, ySim [B,S] f32
// output: posterior [B] f32
// ---------------------------------------------------------------------------
extern "C" void kernel_launch(void* const* d_in, const int* in_sizes, int n_in,
                              void* d_out, int out_size)
{
    const float* predAbun   = (const float*)d_in[0];
    const float* sigmaPrior = (const float*)d_in[1];
    const float* yReal      = (const float*)d_in[2];
    const float* ySim       = (const float*)d_in[3];
    float* out = (float*)d_out;

    int B  = in_sizes[0] / 7;   // 8192
    int S  = in_sizes[2] / B;   // 4096
    int S4 = S / 4;

    const float SIGMA_L = 0.1f;
    float scale = 1.0f / (2.0f * SIGMA_L * SIGMA_L * (float)S);  // folds mean over S

    int nPriorBlocks = (B + 255) / 256;  // 32 for B=8192 (g_partials holds 256)

    fused_posterior_kernel<<<B, 256>>>(predAbun, sigmaPrior,
                                       (const float4*)yReal, (const float4*)ySim,
                                       out, B, S4, scale, 1.0f / (float)B,
                                       nPriorBlocks);
}